// round 13
// baseline (speedup 1.0000x reference)
#include <cuda_runtime.h>
#include <math.h>

#define BB 512
#define NN 64
#define MH 128
#define NR 32    // rows per block (half batch)

// ---- scratch (allocation-free) ----
__device__ __align__(16) uint2 g_WfP[(MH / 8) * 4 * MH];   // packed tf32 Wfused
__device__ __align__(16) uint2 g_W1P[(MH / 8) * 4 * MH];   // packed tf32 psi_w1
__device__ float g_c0[MH];     // psi_b0 + 63 * phi_b1 @ psi_w0[3:,:]
__device__ float g_sp;         // softplus(bf_scale_raw)
// pre-halved phi weights
__device__ __align__(16) float g_Wvd[3 * MH];  // 0.5*(W0[3+d]-W0[6+d])
__device__ __align__(16) float g_Wus[3 * MH];  // 0.5*(W0[d]+W0[6+d])
__device__ __align__(16) float g_w9h[MH];
__device__ __align__(16) float g_w10h[MH];
__device__ __align__(16) float g_bh[MH];

__device__ __forceinline__ float tanh_apx(float v) {
    float y; asm("tanh.approx.f32 %0, %1;" : "=f"(y) : "f"(v)); return y;
}
__device__ __forceinline__ float silu_f(float q) {
    float qh = 0.5f * q;
    float th = tanh_apx(qh);
    return fmaf(qh, th, qh);
}
__device__ __forceinline__ unsigned tf32r(float f) {
    unsigned u; asm("cvt.rna.tf32.f32 %0, %1;" : "=r"(u) : "f"(f)); return u;
}
__device__ __forceinline__ float tf32f(float f) {
    return __uint_as_float(tf32r(f));
}
__device__ __forceinline__ void mma_tf32(float c[4], unsigned a0, unsigned a1,
                                         unsigned a2, unsigned a3,
                                         unsigned b0, unsigned b1) {
    asm("mma.sync.aligned.m16n8k8.row.col.f32.tf32.tf32.f32 "
        "{%0,%1,%2,%3}, {%4,%5,%6,%7}, {%8,%9}, {%0,%1,%2,%3};"
        : "+f"(c[0]), "+f"(c[1]), "+f"(c[2]), "+f"(c[3])
        : "r"(a0), "r"(a1), "r"(a2), "r"(a3), "r"(b0), "r"(b1));
}

// ---------------------------------------------------------------------------
// Kernel 0: precompute v4 — 4 threads/output + phi weight prep.
// 129 blocks x 512 threads.
// ---------------------------------------------------------------------------
__global__ __launch_bounds__(512) void precompute_kernel(
    const float* __restrict__ phi_w1, const float* __restrict__ phi_b1,
    const float* __restrict__ psi_w0, const float* __restrict__ psi_b0,
    const float* __restrict__ psi_w1, const float* __restrict__ W0,
    const float* __restrict__ b0, const float* __restrict__ bf_scale_raw)
{
    __shared__ float row[MH];
    int t = threadIdx.x;           // 0..511
    int k = blockIdx.x;            // 0..128
    int o = t >> 2;                // output channel 0..127
    int p = t & 3;                 // k-part 0..3
    if (t < MH) row[t] = (k < MH) ? phi_w1[k * MH + t] : phi_b1[t];
    __syncthreads();

    const float* W = psi_w0 + (3 + p * 32) * MH + o;
    const float* rp = row + p * 32;
    float a0 = 0.f, a1 = 0.f, a2 = 0.f, a3 = 0.f;
    #pragma unroll 8
    for (int m = 0; m < 32; m += 4) {
        a0 = fmaf(rp[m + 0], W[(m + 0) * MH], a0);
        a1 = fmaf(rp[m + 1], W[(m + 1) * MH], a1);
        a2 = fmaf(rp[m + 2], W[(m + 2) * MH], a2);
        a3 = fmaf(rp[m + 3], W[(m + 3) * MH], a3);
    }
    float acc = (a0 + a1) + (a2 + a3);
    acc += __shfl_xor_sync(0xffffffffu, acc, 1);
    acc += __shfl_xor_sync(0xffffffffu, acc, 2);

    if (k < MH) {
        if (p == 0) {
            int kt = k >> 3, s = k & 7;
            unsigned wf = tf32r(acc);
            unsigned w1 = tf32r(psi_w1[k * MH + o]);
            int idx = (kt * 4 + (s & 3)) * MH + o;
            if (s < 4) { g_WfP[idx].x = wf; g_W1P[idx].x = w1; }
            else       { g_WfP[idx].y = wf; g_W1P[idx].y = w1; }
        }
    } else {
        if (p == 0) {
            g_c0[o] = psi_b0[o] + 63.0f * acc;
            if (o == 0) {
                float v = bf_scale_raw[0];
                g_sp = (v > 20.0f) ? v : log1pf(__expf(v));
            }
        }
        // phi weight prep
        if (t < 3 * MH) {
            int d = t >> 7, oo = t & 127;
            g_Wvd[t] = 0.5f * (W0[(3 + d) * MH + oo] - W0[(6 + d) * MH + oo]);
            g_Wus[t] = 0.5f * (W0[d * MH + oo] + W0[(6 + d) * MH + oo]);
        }
        if (t < MH) {
            g_w9h[t]  = 0.5f * W0[9 * MH + t];
            g_w10h[t] = 0.5f * W0[10 * MH + t];
            g_bh[t]   = 0.5f * b0[t];
        }
    }
}

// ---------------------------------------------------------------------------
// Fused kernel: 1024 blocks = (batch, 32-row half) x 256 threads, 3 CTAs/SM.
// Phase 1 (phi): warp w owns local rows w*4..+3; lane l owns ch 4l..4l+3.
//   silu = linear (closed form from column sums) + tanh part.
// Phase 2 (psi): rows R0..R0+31 only (row-local), tf32 mma, 16x32 per warp.
// H / h1 stored in smem pre-converted to tf32 (idempotent -> bitwise same mma).
// ---------------------------------------------------------------------------
__global__ __launch_bounds__(256, 3) void fused_kernel(
    const float* __restrict__ x,
    const float* __restrict__ psi_w0, const float* __restrict__ psi_b1,
    const float* __restrict__ psi_w2, const float* __restrict__ psi_b2,
    float* __restrict__ out)
{
    __shared__ __align__(16) float vs[NN * MH];    // 32KB; later H (stride 132)
    __shared__ __align__(16) float r1s[NN * NR];   // [j][li] 8KB
    __shared__ float SV[MH];
    __shared__ float S1[NR];
    __shared__ float S2[NR];
    __shared__ float part[4 * NR * 3];             // [nh][row][oc]

    int blk = blockIdx.x;
    int b = blk >> 1, R0 = (blk & 1) * NR;
    int t = threadIdx.x;
    int w = t >> 5, l = t & 31;
    int lw = w * 4;          // local row base for this warp (phi)
    int kc = l * 4;
    const float* xb = x + b * (NN * 3);
    float* sb = vs;          // phase2: H/h1, 32 rows stride 132 (<=4224)

    // ---------------- Phase 1 setup ----------------
    // vs: thread owns column k = t&127, j-half = t>>7; weights in registers
    {
        int k = t & 127, jh = t >> 7;
        float wd0 = g_Wvd[k], wd1 = g_Wvd[MH + k], wd2 = g_Wvd[2 * MH + k];
        const float* xj = xb + jh * 96;
        float* vcol = vs + jh * 32 * MH + k;
        #pragma unroll 4
        for (int j = 0; j < 32; j++) {
            float vv = xj[j * 3 + 0] * wd0;
            vv = fmaf(xj[j * 3 + 1], wd1, vv);
            vv = fmaf(xj[j * 3 + 2], wd2, vv);
            vcol[j * MH] = vv;   // already halved
        }
    }
    for (int idx = t; idx < NN * NR; idx += 256) {
        int j = idx >> 5, li = idx & 31;
        int i = R0 + li;
        float d0 = xb[i * 3 + 0] - xb[j * 3 + 0];
        float d1 = xb[i * 3 + 1] - xb[j * 3 + 1];
        float d2 = xb[i * 3 + 2] - xb[j * 3 + 2];
        r1s[idx] = sqrtf(fmaf(d0, d0, fmaf(d1, d1, fmaf(d2, d2, 1e-12f))));
    }

    float w9h[4], w10h[4];
    float u[4][4];
    {
        float4 q0 = *(const float4*)&g_Wus[kc];
        float4 q1 = *(const float4*)&g_Wus[MH + kc];
        float4 q2 = *(const float4*)&g_Wus[2 * MH + kc];
        float4 q9 = *(const float4*)&g_w9h[kc];
        float4 qa = *(const float4*)&g_w10h[kc];
        float4 qb = *(const float4*)&g_bh[kc];
        float ws0[4] = {q0.x, q0.y, q0.z, q0.w};
        float ws1[4] = {q1.x, q1.y, q1.z, q1.w};
        float ws2[4] = {q2.x, q2.y, q2.z, q2.w};
        float bh[4]  = {qb.x, qb.y, qb.z, qb.w};
        w9h[0] = q9.x; w9h[1] = q9.y; w9h[2] = q9.z; w9h[3] = q9.w;
        w10h[0] = qa.x; w10h[1] = qa.y; w10h[2] = qa.z; w10h[3] = qa.w;
        #pragma unroll
        for (int ii = 0; ii < 4; ii++) {
            int i = R0 + lw + ii;
            float xi0 = xb[i * 3 + 0], xi1 = xb[i * 3 + 1], xi2 = xb[i * 3 + 2];
            #pragma unroll
            for (int c = 0; c < 4; c++)
                u[ii][c] = fmaf(xi2, ws2[c],
                           fmaf(xi1, ws1[c], fmaf(xi0, ws0[c], bh[c])));
        }
    }
    __syncthreads();

    // ---------------- column sums (own region, no aliasing) ----------------
    if (t < NR) {
        float s1 = 0.f, s2 = 0.f;
        #pragma unroll 8
        for (int j = 0; j < NN; j++) {
            float r1 = r1s[j * NR + t];
            s1 += r1;
            s2 += fmaf(r1, r1, -1e-12f);
        }
        S1[t] = s1; S2[t] = s2;
    } else if (t < NR + MH) {
        int c = t - NR;
        float sv = 0.f;
        #pragma unroll 8
        for (int j = 0; j < NN; j++) sv += vs[j * MH + c];
        SV[c] = sv;
    }

    // ---------------- Phase 1 main loop: tanh part only ----------------
    float acc[4][4];
    #pragma unroll
    for (int ii = 0; ii < 4; ii++)
        #pragma unroll
        for (int c = 0; c < 4; c++) acc[ii][c] = 0.0f;

    const float4* vs4 = (const float4*)vs;
    #pragma unroll 2
    for (int j = 0; j < NN; j++) {
        float4 v4 = vs4[j * 32 + l];
        float vc[4] = {v4.x, v4.y, v4.z, v4.w};
        float4 ra = *(const float4*)&r1s[j * NR + lw];
        float r1v[4] = {ra.x, ra.y, ra.z, ra.w};
        #pragma unroll
        for (int ii = 0; ii < 4; ii++) {
            float r1 = r1v[ii];
            float r2 = fmaf(r1, r1, -1e-12f);
            #pragma unroll
            for (int c = 0; c < 4; c++) {
                float qh = fmaf(r1, w9h[c], fmaf(r2, w10h[c], u[ii][c] + vc[c]));
                float th = tanh_apx(qh);
                acc[ii][c] = fmaf(qh, th, acc[ii][c]);   // tanh part only
            }
        }
    }
    // subtract full diagonal silu (linear sums include j==i)
    #pragma unroll
    for (int ii = 0; ii < 4; ii++) {
        int li = lw + ii;
        int ig = R0 + li;
        float4 v4 = vs4[ig * 32 + l];
        float vc[4] = {v4.x, v4.y, v4.z, v4.w};
        float r1 = r1s[ig * NR + li];
        float r2 = fmaf(r1, r1, -1e-12f);
        #pragma unroll
        for (int c = 0; c < 4; c++) {
            float qh = fmaf(r1, w9h[c], fmaf(r2, w10h[c], u[ii][c] + vc[c]));
            float th = tanh_apx(qh);
            acc[ii][c] -= fmaf(qh, th, qh);   // qh + qh*th
        }
    }
    __syncthreads();   // all vs/r1s reads retired (sums done pre-loop)

    // H = linear + acc ; overlay into sb (stride 132), pre-rounded to tf32
    #pragma unroll
    for (int ii = 0; ii < 4; ii++) {
        int li = lw + ii;
        float s1 = S1[li], s2 = S2[li];
        float hv[4];
        #pragma unroll
        for (int c = 0; c < 4; c++) {
            float lin = fmaf(64.0f, u[ii][c], SV[kc + c]);
            lin = fmaf(w9h[c], s1, lin);
            lin = fmaf(w10h[c], s2, lin);
            hv[c] = tf32f(lin + acc[ii][c]);
        }
        *(float4*)&sb[li * 132 + kc] = make_float4(hv[0], hv[1], hv[2], hv[3]);
    }
    __syncthreads();

    // ---------------- Phase 2: psi via tf32 mma (rows R0..R0+31) ----------
    int mi = w & 1, nh = w >> 1;     // 2 m-tiles x 4 n-quarters
    int gi = l >> 2, qi = l & 3;
    int rA = mi * 16 + gi;           // local rows rA, rA+8
    int nbase = nh * 32;

    float C[4][4];
    int gr0 = R0 + rA, gr1 = R0 + rA + 8;
    float xr0[3] = {xb[gr0 * 3 + 0], xb[gr0 * 3 + 1], xb[gr0 * 3 + 2]};
    float xr1[3] = {xb[gr1 * 3 + 0], xb[gr1 * 3 + 1], xb[gr1 * 3 + 2]};

    #pragma unroll
    for (int tt = 0; tt < 4; tt++) {
        int nc = nbase + tt * 8 + qi * 2;
        #pragma unroll
        for (int h = 0; h < 2; h++) {
            float cc = g_c0[nc + h];
            float p0 = psi_w0[0 * MH + nc + h];
            float p1 = psi_w0[1 * MH + nc + h];
            float p2 = psi_w0[2 * MH + nc + h];
            C[tt][h]     = fmaf(xr0[2], p2, fmaf(xr0[1], p1, fmaf(xr0[0], p0, cc)));
            C[tt][2 + h] = fmaf(xr1[2], p2, fmaf(xr1[1], p1, fmaf(xr1[0], p0, cc)));
        }
    }

    // layer A: C += H @ Wfused  (smem already tf32-rounded -> raw bits)
    {
        const float* sA0 = &sb[rA * 132];
        const float* sA1 = &sb[(rA + 8) * 132];
        const uint2* wp = &g_WfP[qi * MH + nbase + gi];
        #pragma unroll 1
        for (int kt = 0; kt < 16; kt++) {
            int k0 = kt * 8;
            unsigned a0 = __float_as_uint(sA0[k0 + qi]);
            unsigned a1 = __float_as_uint(sA1[k0 + qi]);
            unsigned a2 = __float_as_uint(sA0[k0 + qi + 4]);
            unsigned a3 = __float_as_uint(sA1[k0 + qi + 4]);
            #pragma unroll
            for (int tt = 0; tt < 4; tt++) {
                uint2 bb = wp[tt * 8];
                mma_tf32(C[tt], a0, a1, a2, a3, bb.x, bb.y);
            }
            wp += 4 * MH;
        }
    }
    __syncthreads();

    // silu -> h1 in shared (pre-rounded to tf32)
    #pragma unroll
    for (int tt = 0; tt < 4; tt++) {
        int nc = nbase + tt * 8 + qi * 2;
        *(float2*)&sb[rA * 132 + nc] =
            make_float2(tf32f(silu_f(C[tt][0])), tf32f(silu_f(C[tt][1])));
        *(float2*)&sb[(rA + 8) * 132 + nc] =
            make_float2(tf32f(silu_f(C[tt][2])), tf32f(silu_f(C[tt][3])));
    }
    __syncthreads();

    // layer B: C = psi_b1 + h1 @ psi_w1
    #pragma unroll
    for (int tt = 0; tt < 4; tt++) {
        int nc = nbase + tt * 8 + qi * 2;
        float bb0 = psi_b1[nc], bb1 = psi_b1[nc + 1];
        C[tt][0] = bb0; C[tt][1] = bb1; C[tt][2] = bb0; C[tt][3] = bb1;
    }
    {
        const float* sA0 = &sb[rA * 132];
        const float* sA1 = &sb[(rA + 8) * 132];
        const uint2* wp = &g_W1P[qi * MH + nbase + gi];
        #pragma unroll 1
        for (int kt = 0; kt < 16; kt++) {
            int k0 = kt * 8;
            unsigned a0 = __float_as_uint(sA0[k0 + qi]);
            unsigned a1 = __float_as_uint(sA1[k0 + qi]);
            unsigned a2 = __float_as_uint(sA0[k0 + qi + 4]);
            unsigned a3 = __float_as_uint(sA1[k0 + qi + 4]);
            #pragma unroll
            for (int tt = 0; tt < 4; tt++) {
                uint2 bb = wp[tt * 8];
                mma_tf32(C[tt], a0, a1, a2, a3, bb.x, bb.y);
            }
            wp += 4 * MH;
        }
    }

    // layer C: silu -> partial projection onto psi_w2 (exact fp32)
    float p0[3] = {0.f, 0.f, 0.f}, p1[3] = {0.f, 0.f, 0.f};
    #pragma unroll
    for (int tt = 0; tt < 4; tt++) {
        int nc = nbase + tt * 8 + qi * 2;
        float s00 = silu_f(C[tt][0]), s01 = silu_f(C[tt][1]);
        float s10 = silu_f(C[tt][2]), s11 = silu_f(C[tt][3]);
        #pragma unroll
        for (int oc = 0; oc < 3; oc++) {
            float wa = psi_w2[nc * 3 + oc];
            float wb = psi_w2[(nc + 1) * 3 + oc];
            p0[oc] = fmaf(s01, wb, fmaf(s00, wa, p0[oc]));
            p1[oc] = fmaf(s11, wb, fmaf(s10, wa, p1[oc]));
        }
    }
    #pragma unroll
    for (int oc = 0; oc < 3; oc++) {
        p0[oc] += __shfl_xor_sync(0xffffffffu, p0[oc], 1);
        p0[oc] += __shfl_xor_sync(0xffffffffu, p0[oc], 2);
        p1[oc] += __shfl_xor_sync(0xffffffffu, p1[oc], 1);
        p1[oc] += __shfl_xor_sync(0xffffffffu, p1[oc], 2);
    }
    if (qi == 0) {
        #pragma unroll
        for (int oc = 0; oc < 3; oc++) {
            part[nh * (NR * 3) + rA * 3 + oc] = p0[oc];
            part[nh * (NR * 3) + (rA + 8) * 3 + oc] = p1[oc];
        }
    }
    __syncthreads();

    if (t < NR * 3) {
        int r = t / 3, oc = t - r * 3;
        float p = part[r * 3 + oc] + part[96 + r * 3 + oc]
                + part[192 + r * 3 + oc] + part[288 + r * 3 + oc] + psi_b2[oc];
        out[(b * NN + R0 + r) * 3 + oc] = tanhf(p) * g_sp;
    }
}

// ---------------------------------------------------------------------------
// Inputs (metadata order): 0 x, 1 spin(unused), 2 phi_w0, 3 phi_b0, 4 phi_w1,
// 5 phi_b1, 6 psi_w0, 7 psi_b0, 8 psi_w1, 9 psi_b1, 10 psi_w2, 11 psi_b2,
// 12 bf_scale_raw. Output: float32 (512,64,3).
// ---------------------------------------------------------------------------
extern "C" void kernel_launch(void* const* d_in, const int* in_sizes, int n_in,
                              void* d_out, int out_size)
{
    const float* x      = (const float*)d_in[0];
    const float* phi_w0 = (const float*)d_in[2];
    const float* phi_b0 = (const float*)d_in[3];
    const float* phi_w1 = (const float*)d_in[4];
    const float* phi_b1 = (const float*)d_in[5];
    const float* psi_w0 = (const float*)d_in[6];
    const float* psi_b0 = (const float*)d_in[7];
    const float* psi_w1 = (const float*)d_in[8];
    const float* psi_b1 = (const float*)d_in[9];
    const float* psi_w2 = (const float*)d_in[10];
    const float* psi_b2 = (const float*)d_in[11];
    const float* bf     = (const float*)d_in[12];
    float* out = (float*)d_out;

    precompute_kernel<<<MH + 1, 512>>>(phi_w1, phi_b1, psi_w0, psi_b0,
                                       psi_w1, phi_w0, phi_b0, bf);
    fused_kernel<<<BB * 2, 256>>>(x, psi_w0, psi_b1, psi_w2, psi_b2, out);
}

// round 14
// speedup vs baseline: 1.0092x; 1.0092x over previous
#include <cuda_runtime.h>
#include <math.h>

#define BB 512
#define NN 64
#define MH 128
#define NR 32    // rows per block (half batch)

// ---- scratch (allocation-free) ----
__device__ __align__(16) uint2 g_WfP[(MH / 8) * 4 * MH];   // packed tf32 Wfused
__device__ __align__(16) uint2 g_W1P[(MH / 8) * 4 * MH];   // packed tf32 psi_w1
__device__ float g_c0[MH];     // psi_b0 + 63 * phi_b1 @ psi_w0[3:,:]
__device__ float g_sp;         // softplus(bf_scale_raw)
// pre-halved phi weights
__device__ __align__(16) float g_Wvd[3 * MH];  // 0.5*(W0[3+d]-W0[6+d])
__device__ __align__(16) float g_Wus[3 * MH];  // 0.5*(W0[d]+W0[6+d])
__device__ __align__(16) float g_w9h[MH];
__device__ __align__(16) float g_w10h[MH];
__device__ __align__(16) float g_bh[MH];

__device__ __forceinline__ float tanh_apx(float v) {
    float y; asm("tanh.approx.f32 %0, %1;" : "=f"(y) : "f"(v)); return y;
}
__device__ __forceinline__ float silu_f(float q) {
    float qh = 0.5f * q;
    float th = tanh_apx(qh);
    return fmaf(qh, th, qh);
}
__device__ __forceinline__ unsigned tf32r(float f) {
    unsigned u; asm("cvt.rna.tf32.f32 %0, %1;" : "=r"(u) : "f"(f)); return u;
}
__device__ __forceinline__ float tf32f(float f) {
    return __uint_as_float(tf32r(f));
}
__device__ __forceinline__ void mma_tf32(float c[4], unsigned a0, unsigned a1,
                                         unsigned a2, unsigned a3,
                                         unsigned b0, unsigned b1) {
    asm("mma.sync.aligned.m16n8k8.row.col.f32.tf32.tf32.f32 "
        "{%0,%1,%2,%3}, {%4,%5,%6,%7}, {%8,%9}, {%0,%1,%2,%3};"
        : "+f"(c[0]), "+f"(c[1]), "+f"(c[2]), "+f"(c[3])
        : "r"(a0), "r"(a1), "r"(a2), "r"(a3), "r"(b0), "r"(b1));
}

// ---------------------------------------------------------------------------
// Kernel 0: precompute v4 — 4 threads/output + phi weight prep.
// 129 blocks x 512 threads.
// ---------------------------------------------------------------------------
__global__ __launch_bounds__(512) void precompute_kernel(
    const float* __restrict__ phi_w1, const float* __restrict__ phi_b1,
    const float* __restrict__ psi_w0, const float* __restrict__ psi_b0,
    const float* __restrict__ psi_w1, const float* __restrict__ W0,
    const float* __restrict__ b0, const float* __restrict__ bf_scale_raw)
{
    __shared__ float row[MH];
    int t = threadIdx.x;           // 0..511
    int k = blockIdx.x;            // 0..128
    int o = t >> 2;                // output channel 0..127
    int p = t & 3;                 // k-part 0..3
    if (t < MH) row[t] = (k < MH) ? phi_w1[k * MH + t] : phi_b1[t];
    __syncthreads();

    const float* W = psi_w0 + (3 + p * 32) * MH + o;
    const float* rp = row + p * 32;
    float a0 = 0.f, a1 = 0.f, a2 = 0.f, a3 = 0.f;
    #pragma unroll 8
    for (int m = 0; m < 32; m += 4) {
        a0 = fmaf(rp[m + 0], W[(m + 0) * MH], a0);
        a1 = fmaf(rp[m + 1], W[(m + 1) * MH], a1);
        a2 = fmaf(rp[m + 2], W[(m + 2) * MH], a2);
        a3 = fmaf(rp[m + 3], W[(m + 3) * MH], a3);
    }
    float acc = (a0 + a1) + (a2 + a3);
    acc += __shfl_xor_sync(0xffffffffu, acc, 1);
    acc += __shfl_xor_sync(0xffffffffu, acc, 2);

    if (k < MH) {
        if (p == 0) {
            int kt = k >> 3, s = k & 7;
            unsigned wf = tf32r(acc);
            unsigned w1 = tf32r(psi_w1[k * MH + o]);
            int idx = (kt * 4 + (s & 3)) * MH + o;
            if (s < 4) { g_WfP[idx].x = wf; g_W1P[idx].x = w1; }
            else       { g_WfP[idx].y = wf; g_W1P[idx].y = w1; }
        }
    } else {
        if (p == 0) {
            g_c0[o] = psi_b0[o] + 63.0f * acc;
            if (o == 0) {
                float v = bf_scale_raw[0];
                g_sp = (v > 20.0f) ? v : log1pf(__expf(v));
            }
        }
        // phi weight prep
        if (t < 3 * MH) {
            int d = t >> 7, oo = t & 127;
            g_Wvd[t] = 0.5f * (W0[(3 + d) * MH + oo] - W0[(6 + d) * MH + oo]);
            g_Wus[t] = 0.5f * (W0[d * MH + oo] + W0[(6 + d) * MH + oo]);
        }
        if (t < MH) {
            g_w9h[t]  = 0.5f * W0[9 * MH + t];
            g_w10h[t] = 0.5f * W0[10 * MH + t];
            g_bh[t]   = 0.5f * b0[t];
        }
    }
}

// ---------------------------------------------------------------------------
// Fused kernel: 1024 blocks = (batch, 32-row half) x 256 threads, 3 CTAs/SM.
// Phase 1 (phi): warp w owns local rows w*4..+3; lane l owns ch 4l..4l+3.
// Phase 2 (psi): tf32 mma, kt-loops unrolled x2 for LDG MLP.
// ---------------------------------------------------------------------------
__global__ __launch_bounds__(256, 3) void fused_kernel(
    const float* __restrict__ x,
    const float* __restrict__ psi_w0, const float* __restrict__ psi_b1,
    const float* __restrict__ psi_w2, const float* __restrict__ psi_b2,
    float* __restrict__ out)
{
    __shared__ __align__(16) float vs[NN * MH];    // 32KB; later H (stride 132)
    __shared__ __align__(16) float r1s[NN * NR];   // [j][li] 8KB
    __shared__ float SV[MH];
    __shared__ float S1[NR];
    __shared__ float S2[NR];
    __shared__ float part[4 * NR * 3];             // [nh][row][oc]

    int blk = blockIdx.x;
    int b = blk >> 1, R0 = (blk & 1) * NR;
    int t = threadIdx.x;
    int w = t >> 5, l = t & 31;
    int lw = w * 4;          // local row base for this warp (phi)
    int kc = l * 4;
    const float* xb = x + b * (NN * 3);
    float* sb = vs;          // phase2: H/h1, 32 rows stride 132 (<=4224)

    // ---------------- Phase 1 setup ----------------
    // vs: thread owns column k = t&127, j-half = t>>7; weights in registers
    {
        int k = t & 127, jh = t >> 7;
        float wd0 = g_Wvd[k], wd1 = g_Wvd[MH + k], wd2 = g_Wvd[2 * MH + k];
        const float* xj = xb + jh * 96;
        float* vcol = vs + jh * 32 * MH + k;
        #pragma unroll 4
        for (int j = 0; j < 32; j++) {
            float vv = xj[j * 3 + 0] * wd0;
            vv = fmaf(xj[j * 3 + 1], wd1, vv);
            vv = fmaf(xj[j * 3 + 2], wd2, vv);
            vcol[j * MH] = vv;   // already halved
        }
    }
    for (int idx = t; idx < NN * NR; idx += 256) {
        int j = idx >> 5, li = idx & 31;
        int i = R0 + li;
        float d0 = xb[i * 3 + 0] - xb[j * 3 + 0];
        float d1 = xb[i * 3 + 1] - xb[j * 3 + 1];
        float d2 = xb[i * 3 + 2] - xb[j * 3 + 2];
        r1s[idx] = sqrtf(fmaf(d0, d0, fmaf(d1, d1, fmaf(d2, d2, 1e-12f))));
    }

    float w9h[4], w10h[4];
    float u[4][4];
    {
        float4 q0 = *(const float4*)&g_Wus[kc];
        float4 q1 = *(const float4*)&g_Wus[MH + kc];
        float4 q2 = *(const float4*)&g_Wus[2 * MH + kc];
        float4 q9 = *(const float4*)&g_w9h[kc];
        float4 qa = *(const float4*)&g_w10h[kc];
        float4 qb = *(const float4*)&g_bh[kc];
        float ws0[4] = {q0.x, q0.y, q0.z, q0.w};
        float ws1[4] = {q1.x, q1.y, q1.z, q1.w};
        float ws2[4] = {q2.x, q2.y, q2.z, q2.w};
        float bh[4]  = {qb.x, qb.y, qb.z, qb.w};
        w9h[0] = q9.x; w9h[1] = q9.y; w9h[2] = q9.z; w9h[3] = q9.w;
        w10h[0] = qa.x; w10h[1] = qa.y; w10h[2] = qa.z; w10h[3] = qa.w;
        #pragma unroll
        for (int ii = 0; ii < 4; ii++) {
            int i = R0 + lw + ii;
            float xi0 = xb[i * 3 + 0], xi1 = xb[i * 3 + 1], xi2 = xb[i * 3 + 2];
            #pragma unroll
            for (int c = 0; c < 4; c++)
                u[ii][c] = fmaf(xi2, ws2[c],
                           fmaf(xi1, ws1[c], fmaf(xi0, ws0[c], bh[c])));
        }
    }
    __syncthreads();

    // ---------------- column sums ----------------
    if (t < NR) {
        float s1 = 0.f, s2 = 0.f;
        #pragma unroll 8
        for (int j = 0; j < NN; j++) {
            float r1 = r1s[j * NR + t];
            s1 += r1;
            s2 += fmaf(r1, r1, -1e-12f);
        }
        S1[t] = s1; S2[t] = s2;
    } else if (t < NR + MH) {
        int c = t - NR;
        float sv = 0.f;
        #pragma unroll 8
        for (int j = 0; j < NN; j++) sv += vs[j * MH + c];
        SV[c] = sv;
    }

    // ---------------- Phase 1 main loop: tanh part only ----------------
    float acc[4][4];
    #pragma unroll
    for (int ii = 0; ii < 4; ii++)
        #pragma unroll
        for (int c = 0; c < 4; c++) acc[ii][c] = 0.0f;

    const float4* vs4 = (const float4*)vs;
    #pragma unroll 2
    for (int j = 0; j < NN; j++) {
        float4 v4 = vs4[j * 32 + l];
        float vc[4] = {v4.x, v4.y, v4.z, v4.w};
        float4 ra = *(const float4*)&r1s[j * NR + lw];
        float r1v[4] = {ra.x, ra.y, ra.z, ra.w};
        #pragma unroll
        for (int ii = 0; ii < 4; ii++) {
            float r1 = r1v[ii];
            float r2 = fmaf(r1, r1, -1e-12f);
            #pragma unroll
            for (int c = 0; c < 4; c++) {
                float qh = fmaf(r1, w9h[c], fmaf(r2, w10h[c], u[ii][c] + vc[c]));
                float th = tanh_apx(qh);
                acc[ii][c] = fmaf(qh, th, acc[ii][c]);   // tanh part only
            }
        }
    }
    // subtract full diagonal silu (linear sums include j==i)
    #pragma unroll
    for (int ii = 0; ii < 4; ii++) {
        int li = lw + ii;
        int ig = R0 + li;
        float4 v4 = vs4[ig * 32 + l];
        float vc[4] = {v4.x, v4.y, v4.z, v4.w};
        float r1 = r1s[ig * NR + li];
        float r2 = fmaf(r1, r1, -1e-12f);
        #pragma unroll
        for (int c = 0; c < 4; c++) {
            float qh = fmaf(r1, w9h[c], fmaf(r2, w10h[c], u[ii][c] + vc[c]));
            float th = tanh_apx(qh);
            acc[ii][c] -= fmaf(qh, th, qh);   // qh + qh*th
        }
    }
    __syncthreads();   // all vs/r1s reads retired (sums done pre-loop)

    // H = linear + acc ; overlay into sb (stride 132), pre-rounded to tf32
    #pragma unroll
    for (int ii = 0; ii < 4; ii++) {
        int li = lw + ii;
        float s1 = S1[li], s2 = S2[li];
        float hv[4];
        #pragma unroll
        for (int c = 0; c < 4; c++) {
            float lin = fmaf(64.0f, u[ii][c], SV[kc + c]);
            lin = fmaf(w9h[c], s1, lin);
            lin = fmaf(w10h[c], s2, lin);
            hv[c] = tf32f(lin + acc[ii][c]);
        }
        *(float4*)&sb[li * 132 + kc] = make_float4(hv[0], hv[1], hv[2], hv[3]);
    }
    __syncthreads();

    // ---------------- Phase 2: psi via tf32 mma (rows R0..R0+31) ----------
    int mi = w & 1, nh = w >> 1;     // 2 m-tiles x 4 n-quarters
    int gi = l >> 2, qi = l & 3;
    int rA = mi * 16 + gi;           // local rows rA, rA+8
    int nbase = nh * 32;

    float C[4][4];
    int gr0 = R0 + rA, gr1 = R0 + rA + 8;
    float xr0[3] = {xb[gr0 * 3 + 0], xb[gr0 * 3 + 1], xb[gr0 * 3 + 2]};
    float xr1[3] = {xb[gr1 * 3 + 0], xb[gr1 * 3 + 1], xb[gr1 * 3 + 2]};

    #pragma unroll
    for (int tt = 0; tt < 4; tt++) {
        int nc = nbase + tt * 8 + qi * 2;
        #pragma unroll
        for (int h = 0; h < 2; h++) {
            float cc = g_c0[nc + h];
            float p0 = psi_w0[0 * MH + nc + h];
            float p1 = psi_w0[1 * MH + nc + h];
            float p2 = psi_w0[2 * MH + nc + h];
            C[tt][h]     = fmaf(xr0[2], p2, fmaf(xr0[1], p1, fmaf(xr0[0], p0, cc)));
            C[tt][2 + h] = fmaf(xr1[2], p2, fmaf(xr1[1], p1, fmaf(xr1[0], p0, cc)));
        }
    }

    // layer A: C += H @ Wfused  (kt unrolled x2 for LDG MLP)
    {
        const float* sA0 = &sb[rA * 132];
        const float* sA1 = &sb[(rA + 8) * 132];
        const uint2* wp = &g_WfP[qi * MH + nbase + gi];
        #pragma unroll 1
        for (int kt = 0; kt < 16; kt += 2) {
            int k0 = kt * 8;
            unsigned a0 = __float_as_uint(sA0[k0 + qi]);
            unsigned a1 = __float_as_uint(sA1[k0 + qi]);
            unsigned a2 = __float_as_uint(sA0[k0 + qi + 4]);
            unsigned a3 = __float_as_uint(sA1[k0 + qi + 4]);
            unsigned a4 = __float_as_uint(sA0[k0 + 8 + qi]);
            unsigned a5 = __float_as_uint(sA1[k0 + 8 + qi]);
            unsigned a6 = __float_as_uint(sA0[k0 + 8 + qi + 4]);
            unsigned a7 = __float_as_uint(sA1[k0 + 8 + qi + 4]);
            uint2 bbA[4], bbB[4];
            #pragma unroll
            for (int tt = 0; tt < 4; tt++) {
                bbA[tt] = wp[tt * 8];
                bbB[tt] = wp[4 * MH + tt * 8];
            }
            #pragma unroll
            for (int tt = 0; tt < 4; tt++)
                mma_tf32(C[tt], a0, a1, a2, a3, bbA[tt].x, bbA[tt].y);
            #pragma unroll
            for (int tt = 0; tt < 4; tt++)
                mma_tf32(C[tt], a4, a5, a6, a7, bbB[tt].x, bbB[tt].y);
            wp += 8 * MH;
        }
    }
    __syncthreads();

    // silu -> h1 in shared (pre-rounded to tf32)
    #pragma unroll
    for (int tt = 0; tt < 4; tt++) {
        int nc = nbase + tt * 8 + qi * 2;
        *(float2*)&sb[rA * 132 + nc] =
            make_float2(tf32f(silu_f(C[tt][0])), tf32f(silu_f(C[tt][1])));
        *(float2*)&sb[(rA + 8) * 132 + nc] =
            make_float2(tf32f(silu_f(C[tt][2])), tf32f(silu_f(C[tt][3])));
    }
    __syncthreads();

    // layer B: C = psi_b1 + h1 @ psi_w1  (kt unrolled x2)
    #pragma unroll
    for (int tt = 0; tt < 4; tt++) {
        int nc = nbase + tt * 8 + qi * 2;
        float bb0 = psi_b1[nc], bb1 = psi_b1[nc + 1];
        C[tt][0] = bb0; C[tt][1] = bb1; C[tt][2] = bb0; C[tt][3] = bb1;
    }
    {
        const float* sA0 = &sb[rA * 132];
        const float* sA1 = &sb[(rA + 8) * 132];
        const uint2* wp = &g_W1P[qi * MH + nbase + gi];
        #pragma unroll 1
        for (int kt = 0; kt < 16; kt += 2) {
            int k0 = kt * 8;
            unsigned a0 = __float_as_uint(sA0[k0 + qi]);
            unsigned a1 = __float_as_uint(sA1[k0 + qi]);
            unsigned a2 = __float_as_uint(sA0[k0 + qi + 4]);
            unsigned a3 = __float_as_uint(sA1[k0 + qi + 4]);
            unsigned a4 = __float_as_uint(sA0[k0 + 8 + qi]);
            unsigned a5 = __float_as_uint(sA1[k0 + 8 + qi]);
            unsigned a6 = __float_as_uint(sA0[k0 + 8 + qi + 4]);
            unsigned a7 = __float_as_uint(sA1[k0 + 8 + qi + 4]);
            uint2 bbA[4], bbB[4];
            #pragma unroll
            for (int tt = 0; tt < 4; tt++) {
                bbA[tt] = wp[tt * 8];
                bbB[tt] = wp[4 * MH + tt * 8];
            }
            #pragma unroll
            for (int tt = 0; tt < 4; tt++)
                mma_tf32(C[tt], a0, a1, a2, a3, bbA[tt].x, bbA[tt].y);
            #pragma unroll
            for (int tt = 0; tt < 4; tt++)
                mma_tf32(C[tt], a4, a5, a6, a7, bbB[tt].x, bbB[tt].y);
            wp += 8 * MH;
        }
    }

    // layer C: silu -> partial projection onto psi_w2 (exact fp32)
    float p0[3] = {0.f, 0.f, 0.f}, p1[3] = {0.f, 0.f, 0.f};
    #pragma unroll
    for (int tt = 0; tt < 4; tt++) {
        int nc = nbase + tt * 8 + qi * 2;
        float s00 = silu_f(C[tt][0]), s01 = silu_f(C[tt][1]);
        float s10 = silu_f(C[tt][2]), s11 = silu_f(C[tt][3]);
        #pragma unroll
        for (int oc = 0; oc < 3; oc++) {
            float wa = psi_w2[nc * 3 + oc];
            float wb = psi_w2[(nc + 1) * 3 + oc];
            p0[oc] = fmaf(s01, wb, fmaf(s00, wa, p0[oc]));
            p1[oc] = fmaf(s11, wb, fmaf(s10, wa, p1[oc]));
        }
    }
    #pragma unroll
    for (int oc = 0; oc < 3; oc++) {
        p0[oc] += __shfl_xor_sync(0xffffffffu, p0[oc], 1);
        p0[oc] += __shfl_xor_sync(0xffffffffu, p0[oc], 2);
        p1[oc] += __shfl_xor_sync(0xffffffffu, p1[oc], 1);
        p1[oc] += __shfl_xor_sync(0xffffffffu, p1[oc], 2);
    }
    if (qi == 0) {
        #pragma unroll
        for (int oc = 0; oc < 3; oc++) {
            part[nh * (NR * 3) + rA * 3 + oc] = p0[oc];
            part[nh * (NR * 3) + (rA + 8) * 3 + oc] = p1[oc];
        }
    }
    __syncthreads();

    if (t < NR * 3) {
        int r = t / 3, oc = t - r * 3;
        float p = part[r * 3 + oc] + part[96 + r * 3 + oc]
                + part[192 + r * 3 + oc] + part[288 + r * 3 + oc] + psi_b2[oc];
        out[(b * NN + R0 + r) * 3 + oc] = tanhf(p) * g_sp;
    }
}

// ---------------------------------------------------------------------------
// Inputs (metadata order): 0 x, 1 spin(unused), 2 phi_w0, 3 phi_b0, 4 phi_w1,
// 5 phi_b1, 6 psi_w0, 7 psi_b0, 8 psi_w1, 9 psi_b1, 10 psi_w2, 11 psi_b2,
// 12 bf_scale_raw. Output: float32 (512,64,3).
// ---------------------------------------------------------------------------
extern "C" void kernel_launch(void* const* d_in, const int* in_sizes, int n_in,
                              void* d_out, int out_size)
{
    const float* x      = (const float*)d_in[0];
    const float* phi_w0 = (const float*)d_in[2];
    const float* phi_b0 = (const float*)d_in[3];
    const float* phi_w1 = (const float*)d_in[4];
    const float* phi_b1 = (const float*)d_in[5];
    const float* psi_w0 = (const float*)d_in[6];
    const float* psi_b0 = (const float*)d_in[7];
    const float* psi_w1 = (const float*)d_in[8];
    const float* psi_b1 = (const float*)d_in[9];
    const float* psi_w2 = (const float*)d_in[10];
    const float* psi_b2 = (const float*)d_in[11];
    const float* bf     = (const float*)d_in[12];
    float* out = (float*)d_out;

    precompute_kernel<<<MH + 1, 512>>>(phi_w1, phi_b1, psi_w0, psi_b0,
                                       psi_w1, phi_w0, phi_b0, bf);
    fused_kernel<<<BB * 2, 256>>>(x, psi_w0, psi_b1, psi_w2, psi_b2, out);
}